// round 4
// baseline (speedup 1.0000x reference)
#include <cuda_runtime.h>
#include <math.h>

#define N_NODESC 20000
#define WINDOWC  8
#define N_BIGC   160000
#define IN_CC    8
#define HIDC     64
#define E_MAIN   1600000
#define E_DECC   500000
#define DHC      143
#define PSTRIDE  144

// ---------------- scratch (static device globals; no allocation) ----------------
__device__ float g_dis[N_BIGC];
__device__ float g_norm[E_MAIN];
__device__ float g_h[N_BIGC * HIDC];
__device__ float g_agg[N_BIGC * HIDC];
__device__ float g_Xc[N_BIGC * 2 * HIDC];
__device__ float g_gates[N_BIGC * 4 * HIDC];
__device__ float g_y1[N_BIGC * HIDC];
__device__ float g_h2f[N_NODESC * HIDC];
__device__ float g_emb[N_NODESC * DHC];
__device__ float g_Ps[N_NODESC * PSTRIDE];    // col 143 never written -> stays 0
__device__ float g_Pt[N_NODESC * PSTRIDE];
__device__ float g_stats[128];
__device__ float g_bnp[128];

// ---------------- small utility kernels ----------------
__global__ void k_zero(float* p, int n) {
    int i = blockIdx.x * blockDim.x + threadIdx.x;
    if (i < n) p[i] = 0.f;
}

__global__ void k_deg(const int* __restrict__ ei, const float* __restrict__ ea) {
    int i = blockIdx.x * blockDim.x + threadIdx.x;
    if (i < E_MAIN) atomicAdd(&g_dis[ei[E_MAIN + i]], ea[i]);
}

__global__ void k_dis() {
    int i = blockIdx.x * blockDim.x + threadIdx.x;
    if (i < N_BIGC) g_dis[i] = rsqrtf(g_dis[i] + 1.0f);
}

__global__ void k_norm(const int* __restrict__ ei, const float* __restrict__ ea) {
    int i = blockIdx.x * blockDim.x + threadIdx.x;
    if (i < E_MAIN) g_norm[i] = g_dis[ei[i]] * ea[i] * g_dis[ei[E_MAIN + i]];
}

// scatter: 16 threads / edge, float4 gather, one red.global.add.v4
__global__ void k_scatter(const int* __restrict__ ei) {
    int t = blockIdx.x * blockDim.x + threadIdx.x;
    if (t >= E_MAIN * 16) return;
    int e = t >> 4, q = t & 15;
    float nv = g_norm[e];
    const float4* h4 = (const float4*)g_h;
    float4 v = h4[(size_t)ei[e] * 16 + q];
    float4* a = (float4*)(g_agg + (size_t)ei[E_MAIN + e] * 64) + q;
    asm volatile("red.global.add.v4.f32 [%0], {%1,%2,%3,%4};"
                 :: "l"(a), "f"(nv * v.x), "f"(nv * v.y), "f"(nv * v.z), "f"(nv * v.w)
                 : "memory");
}

// y = relu(agg + bias); accumulate per-column sum & sumsq
__global__ void k_brs(const float* __restrict__ bias) {
    __shared__ float ss[256], sq[256];
    int c = threadIdx.x & 63, rg = threadIdx.x >> 6;
    int base = blockIdx.x * 256;
    float bc = bias[c];
    float s = 0.f, s2 = 0.f;
    for (int j = 0; j < 64; j++) {
        int r = base + rg + j * 4;
        float v = g_agg[(size_t)r * 64 + c] + bc;
        v = fmaxf(v, 0.f);
        g_h[(size_t)r * 64 + c] = v;
        s += v; s2 += v * v;
    }
    ss[threadIdx.x] = s; sq[threadIdx.x] = s2;
    __syncthreads();
    if (rg == 0) {
        float a = ss[c] + ss[64 + c] + ss[128 + c] + ss[192 + c];
        float b = sq[c] + sq[64 + c] + sq[128 + c] + sq[192 + c];
        atomicAdd(&g_stats[c], a);
        atomicAdd(&g_stats[64 + c], b);
    }
}

__global__ void k_bnfinal(const float* __restrict__ gam, const float* __restrict__ bet) {
    int c = threadIdx.x;
    if (c < 64) {
        float inv_n = 1.f / (float)N_BIGC;
        float m = g_stats[c] * inv_n;
        float var = g_stats[64 + c] * inv_n - m * m;
        float a = rsqrtf(var + 1e-5f) * gam[c];
        g_bnp[c] = a;
        g_bnp[64 + c] = bet[c] - m * a;
    }
}

__global__ void k_bnapply(int off) {
    int i = blockIdx.x * blockDim.x + threadIdx.x;
    if (i < N_BIGC * HIDC) {
        int c = i & 63, r = i >> 6;
        g_Xc[(size_t)r * 128 + off + c] = g_h[i] * g_bnp[c] + g_bnp[64 + c];
    }
}

// ---------------- tf32 helpers ----------------
__device__ __forceinline__ unsigned f2tf(float f) {
    unsigned u;
    asm("cvt.rna.tf32.f32 %0, %1;" : "=r"(u) : "f"(f));
    return u;
}

#define MMA_TF32(c0,c1,c2,c3,a0,a1,a2,a3,b0,b1)                              \
    asm volatile("mma.sync.aligned.m16n8k8.row.col.f32.tf32.tf32.f32 "       \
                 "{%0,%1,%2,%3}, {%4,%5,%6,%7}, {%8,%9}, {%0,%1,%2,%3};"     \
                 : "+f"(c0), "+f"(c1), "+f"(c2), "+f"(c3)                    \
                 : "r"(a0), "r"(a1), "r"(a2), "r"(a3), "r"(b0), "r"(b1))

// ---------------- tf32 tensor-core GEMM ----------------
// C[M,N] = A[M,K] @ op(B) + bias1 + bias2
// BT=1: B is [N,K] row-major (A@B^T).  BT=0: B is [K,N] row-major.
template <int BT>
__global__ void __launch_bounds__(256, 2)
k_tf32gemm(const float* __restrict__ A, const float* __restrict__ B,
           const float* __restrict__ bias1, const float* __restrict__ bias2,
           float* __restrict__ C, int M, int N, int K,
           int lda, int ldb, int ldc) {
    __shared__ unsigned As[128][33];
    __shared__ unsigned Bs[128][33];
    int tid = threadIdx.x;
    int warp = tid >> 5, lane = tid & 31;
    int wm = warp >> 2, wn = warp & 3;
    int rowBase = blockIdx.y * 128, colBase = blockIdx.x * 128;
    int lr = lane >> 2, lc = lane & 3;

    float c[4][4][4];
#pragma unroll
    for (int mi = 0; mi < 4; mi++)
#pragma unroll
        for (int ni = 0; ni < 4; ni++)
#pragma unroll
            for (int q = 0; q < 4; q++) c[mi][ni][q] = 0.f;

    for (int k0 = 0; k0 < K; k0 += 32) {
#pragma unroll
        for (int q = 0; q < 16; q++) {
            int idx = q * 256 + tid;
            int r = idx >> 5, kk = idx & 31;
            int gr = rowBase + r, gk = k0 + kk;
            float v = (gr < M && gk < K) ? A[(size_t)gr * lda + gk] : 0.f;
            As[r][kk] = f2tf(v);
        }
        if (BT) {
#pragma unroll
            for (int q = 0; q < 16; q++) {
                int idx = q * 256 + tid;
                int n = idx >> 5, kk = idx & 31;
                int gn = colBase + n, gk = k0 + kk;
                float v = (gn < N && gk < K) ? B[(size_t)gn * ldb + gk] : 0.f;
                Bs[n][kk] = f2tf(v);
            }
        } else {
#pragma unroll
            for (int q = 0; q < 16; q++) {
                int idx = q * 256 + tid;
                int n = idx & 127, kk = idx >> 7;
                int gn = colBase + n, gk = k0 + kk;
                float v = (gn < N && gk < K) ? B[(size_t)gk * ldb + gn] : 0.f;
                Bs[n][kk] = f2tf(v);
            }
        }
        __syncthreads();

#pragma unroll
        for (int ks = 0; ks < 4; ks++) {
            int k8 = ks * 8;
            unsigned a[4][4], b[4][2];
#pragma unroll
            for (int mi = 0; mi < 4; mi++) {
                int r0 = wm * 64 + mi * 16 + lr;
                a[mi][0] = As[r0][k8 + lc];
                a[mi][1] = As[r0 + 8][k8 + lc];
                a[mi][2] = As[r0][k8 + lc + 4];
                a[mi][3] = As[r0 + 8][k8 + lc + 4];
            }
#pragma unroll
            for (int ni = 0; ni < 4; ni++) {
                int n0 = wn * 32 + ni * 8 + lr;
                b[ni][0] = Bs[n0][k8 + lc];
                b[ni][1] = Bs[n0][k8 + lc + 4];
            }
#pragma unroll
            for (int mi = 0; mi < 4; mi++)
#pragma unroll
                for (int ni = 0; ni < 4; ni++)
                    MMA_TF32(c[mi][ni][0], c[mi][ni][1], c[mi][ni][2], c[mi][ni][3],
                             a[mi][0], a[mi][1], a[mi][2], a[mi][3],
                             b[ni][0], b[ni][1]);
        }
        __syncthreads();
    }

#pragma unroll
    for (int mi = 0; mi < 4; mi++) {
#pragma unroll
        for (int ni = 0; ni < 4; ni++) {
            int gr0 = rowBase + wm * 64 + mi * 16 + lr;
            int gc0 = colBase + wn * 32 + ni * 8 + lc * 2;
#pragma unroll
            for (int q = 0; q < 4; q++) {
                int gr = gr0 + (q >> 1) * 8;
                int gc = gc0 + (q & 1);
                if (gr < M && gc < N) {
                    float b = 0.f;
                    if (bias1) b += bias1[gc];
                    if (bias2) b += bias2[gc];
                    C[(size_t)gr * ldc + gc] = c[mi][ni][q] + b;
                }
            }
        }
    }
}

// ---------------- SGEMM N=64 + GCN epilogue: h = A@B; agg = dis^2 * h ----------------
__global__ void k_sgemm64_gcn(const float* __restrict__ A, const float* __restrict__ B,
                              int M, int K, int lda) {
    __shared__ float As[8][132];
    __shared__ float Bs[8][68];
    int tx = threadIdx.x, ty = threadIdx.y;
    int tid = ty * 16 + tx;
    int rowBase = blockIdx.x * 128;
    float acc[8][4];
#pragma unroll
    for (int i = 0; i < 8; i++)
#pragma unroll
        for (int j = 0; j < 4; j++) acc[i][j] = 0.f;

    for (int k0 = 0; k0 < K; k0 += 8) {
#pragma unroll
        for (int q = 0; q < 4; q++) {
            int idx = q * 256 + tid;
            int r = idx >> 3, kk = idx & 7;
            int gr = rowBase + r, gk = k0 + kk;
            As[kk][r] = (gr < M && gk < K) ? A[(size_t)gr * lda + gk] : 0.f;
        }
#pragma unroll
        for (int q = 0; q < 2; q++) {
            int idx = q * 256 + tid;
            int cc = idx & 63, kk = idx >> 6;
            int gk = k0 + kk;
            Bs[kk][cc] = (gk < K) ? B[(size_t)gk * 64 + cc] : 0.f;
        }
        __syncthreads();
#pragma unroll
        for (int kk = 0; kk < 8; kk++) {
            float a[8], b[4];
            *(float4*)(a)     = *(const float4*)&As[kk][ty * 4];
            *(float4*)(a + 4) = *(const float4*)&As[kk][64 + ty * 4];
            *(float4*)(b)     = *(const float4*)&Bs[kk][tx * 4];
#pragma unroll
            for (int i = 0; i < 8; i++)
#pragma unroll
                for (int j = 0; j < 4; j++) acc[i][j] += a[i] * b[j];
        }
        __syncthreads();
    }

#pragma unroll
    for (int i = 0; i < 8; i++) {
        int gr = rowBase + ((i < 4) ? (ty * 4 + i) : (64 + ty * 4 + i - 4));
        if (gr < M) {
            float d = g_dis[gr];
            float d2 = d * d;
#pragma unroll
            for (int j = 0; j < 4; j++) {
                int gc = tx * 4 + j;
                float v = acc[i][j];
                g_h[(size_t)gr * 64 + gc] = v;
                g_agg[(size_t)gr * 64 + gc] = d2 * v;
            }
        }
    }
}

// ---------------- tensor-core LSTM recurrence (all 8 timesteps) ----------------
// Block: 256 thr (8 warps) owns 64 rows. Warp w owns hidden cols [8w,8w+8) of all 4 gates,
// so each thread's accumulator frags hold i,f,g,o for its own (row,col): cell update is
// register-local. h carried as compensated tf32 pair (hi + lo) for accuracy.
__global__ void __launch_bounds__(256, 1)
k_lstm_mma(const float* __restrict__ gates, const float* __restrict__ Whh,
           float* __restrict__ y, float* __restrict__ hfinal, int nrows) {
    extern __shared__ unsigned usm[];
    unsigned (*sW)[68]   = (unsigned(*)[68])usm;                       // [256][68]
    unsigned (*sHhi)[68] = (unsigned(*)[68])(usm + 256 * 68);          // [64][68]
    unsigned (*sHlo)[68] = (unsigned(*)[68])(usm + 256 * 68 + 64 * 68);
    int tid = threadIdx.x, warp = tid >> 5, lane = tid & 31;
    int lr = lane >> 2, lc = lane & 3;

    for (int idx = tid; idx < 256 * 64; idx += 256) {
        int n = idx >> 6, k = idx & 63;
        sW[n][k] = f2tf(Whh[idx]);
    }
    for (int idx = tid; idx < 64 * 68; idx += 256) {
        ((unsigned*)sHhi)[idx] = 0;
        ((unsigned*)sHlo)[idx] = 0;
    }
    __syncthreads();

    int row0 = blockIdx.x * 64;
    float cst[4][4];
#pragma unroll
    for (int mi = 0; mi < 4; mi++)
#pragma unroll
        for (int q = 0; q < 4; q++) cst[mi][q] = 0.f;

    for (int t = 0; t < 8; t++) {
        const float* gt = gates + ((size_t)t * nrows + row0) * 256;
        float acc[4][4][4];
        // init accumulators from precomputed input transform
#pragma unroll
        for (int mi = 0; mi < 4; mi++) {
            int rlo = mi * 16 + lr, rhi = rlo + 8;
            bool vlo = (row0 + rlo) < nrows, vhi = (row0 + rhi) < nrows;
#pragma unroll
            for (int g = 0; g < 4; g++) {
                int col = g * 64 + warp * 8 + lc * 2;
                float2 x0 = vlo ? *(const float2*)(gt + (size_t)rlo * 256 + col)
                                : make_float2(0.f, 0.f);
                float2 x1 = vhi ? *(const float2*)(gt + (size_t)rhi * 256 + col)
                                : make_float2(0.f, 0.f);
                acc[mi][g][0] = x0.x; acc[mi][g][1] = x0.y;
                acc[mi][g][2] = x1.x; acc[mi][g][3] = x1.y;
            }
        }
        // gates += h_{t-1} @ Whh^T  (compensated tf32)
#pragma unroll
        for (int k8 = 0; k8 < 64; k8 += 8) {
            unsigned b[4][2], ahi[4][4], alo[4][4];
#pragma unroll
            for (int g = 0; g < 4; g++) {
                int n0 = g * 64 + warp * 8 + lr;
                b[g][0] = sW[n0][k8 + lc];
                b[g][1] = sW[n0][k8 + lc + 4];
            }
#pragma unroll
            for (int mi = 0; mi < 4; mi++) {
                int r0 = mi * 16 + lr;
                ahi[mi][0] = sHhi[r0][k8 + lc];     ahi[mi][1] = sHhi[r0 + 8][k8 + lc];
                ahi[mi][2] = sHhi[r0][k8 + lc + 4]; ahi[mi][3] = sHhi[r0 + 8][k8 + lc + 4];
                alo[mi][0] = sHlo[r0][k8 + lc];     alo[mi][1] = sHlo[r0 + 8][k8 + lc];
                alo[mi][2] = sHlo[r0][k8 + lc + 4]; alo[mi][3] = sHlo[r0 + 8][k8 + lc + 4];
            }
#pragma unroll
            for (int mi = 0; mi < 4; mi++)
#pragma unroll
                for (int g = 0; g < 4; g++) {
                    MMA_TF32(acc[mi][g][0], acc[mi][g][1], acc[mi][g][2], acc[mi][g][3],
                             ahi[mi][0], ahi[mi][1], ahi[mi][2], ahi[mi][3],
                             b[g][0], b[g][1]);
                    MMA_TF32(acc[mi][g][0], acc[mi][g][1], acc[mi][g][2], acc[mi][g][3],
                             alo[mi][0], alo[mi][1], alo[mi][2], alo[mi][3],
                             b[g][0], b[g][1]);
                }
        }
        __syncthreads();   // all warps done reading h_{t-1}
        // nonlinearity + write h_t
#pragma unroll
        for (int mi = 0; mi < 4; mi++)
#pragma unroll
            for (int q = 0; q < 4; q++) {
                float iv = acc[mi][0][q], fv = acc[mi][1][q];
                float gv = acc[mi][2][q], ov = acc[mi][3][q];
                float si = 1.f / (1.f + expf(-iv));
                float sf = 1.f / (1.f + expf(-fv));
                float so = 1.f / (1.f + expf(-ov));
                float c = sf * cst[mi][q] + si * tanhf(gv);
                cst[mi][q] = c;
                float h = so * tanhf(c);
                int r = mi * 16 + lr + (q >> 1) * 8;
                int col = warp * 8 + lc * 2 + (q & 1);
                unsigned hh = f2tf(h);
                sHhi[r][col] = hh;
                sHlo[r][col] = f2tf(h - __uint_as_float(hh));
                int grow = row0 + r;
                if (grow < nrows) {
                    if (y) y[((size_t)t * nrows + grow) * 64 + col] = h;
                    if (t == 7 && hfinal) hfinal[(size_t)grow * 64 + col] = h;
                }
            }
        __syncthreads();   // h_t fully written before next step's mma
    }
}

// ---------------- node embedding assembly ----------------
__global__ void k_emb(const float* __restrict__ x) {
    int i = blockIdx.x * blockDim.x + threadIdx.x;
    if (i >= N_NODESC * DHC) return;
    int b = i / DHC, j = i - b * DHC;
    float v;
    if (j < 64)       v = g_y1[((size_t)7 * N_NODESC + b) * 64 + j];
    else if (j < 128) v = g_h2f[(size_t)b * 64 + (j - 64)];
    else if (j < 136) v = x[(size_t)b * 8 + (j - 128)];
    else { int t = j - 135; v = x[((size_t)t * N_NODESC + b) * 8 + 7]; }
    g_emb[i] = v;
}

// ---------------- edge decoder: warp per edge, float4 ----------------
__global__ void k_edge(const int* __restrict__ ewi, const float* __restrict__ dWb,
                       const float* __restrict__ dbb, float* __restrict__ out) {
    __shared__ float sw[PSTRIDE];
    if (threadIdx.x < PSTRIDE) sw[threadIdx.x] = (threadIdx.x < DHC) ? dWb[threadIdx.x] : 0.f;
    __syncthreads();
    int warp = (blockIdx.x * blockDim.x + threadIdx.x) >> 5;
    int lane = threadIdx.x & 31;
    if (warp >= E_DECC) return;
    int s = ewi[warp], tg = ewi[E_DECC + warp];
    const float4* ps = (const float4*)(g_Ps + (size_t)s * PSTRIDE);
    const float4* pt = (const float4*)(g_Pt + (size_t)tg * PSTRIDE);
    const float4* sw4 = (const float4*)sw;
    float acc = 0.f;
    {
        float4 a = ps[lane], b = pt[lane], w = sw4[lane];
        acc += fmaxf(a.x + b.x, 0.f) * w.x + fmaxf(a.y + b.y, 0.f) * w.y
             + fmaxf(a.z + b.z, 0.f) * w.z + fmaxf(a.w + b.w, 0.f) * w.w;
        if (lane < 4) {
            float4 a2 = ps[lane + 32], b2 = pt[lane + 32], w2 = sw4[lane + 32];
            acc += fmaxf(a2.x + b2.x, 0.f) * w2.x + fmaxf(a2.y + b2.y, 0.f) * w2.y
                 + fmaxf(a2.z + b2.z, 0.f) * w2.z + fmaxf(a2.w + b2.w, 0.f) * w2.w;
        }
    }
#pragma unroll
    for (int o = 16; o; o >>= 1) acc += __shfl_down_sync(0xffffffffu, acc, o);
    if (lane == 0) out[warp] = acc + dbb[0];
}

// ---------------- host ----------------
extern "C" void kernel_launch(void* const* d_in, const int* in_sizes, int n_in,
                              void* d_out, int out_size) {
    const float *x = 0, *ea = 0;
    const int *ei = 0, *ewi = 0;
    const float* w[20] = {0};
    int wi = 0;
    for (int i = 0; i < n_in; i++) {
        int s = in_sizes[i];
        if      (s == N_BIGC * IN_CC) x   = (const float*)d_in[i];
        else if (s == E_MAIN)         ea  = (const float*)d_in[i];
        else if (s == 2 * E_MAIN)     ei  = (const int*)d_in[i];
        else if (s == 2 * E_DECC)     ewi = (const int*)d_in[i];
        else if (wi < 20)             w[wi++] = (const float*)d_in[i];
    }
    const float *W1 = w[0], *b1 = w[1], *g1 = w[2], *be1 = w[3];
    const float *W2 = w[4], *b2 = w[5], *g2 = w[6], *be2 = w[7];
    const float *Wih1 = w[8], *Whh1 = w[9], *bih1 = w[10], *bhh1 = w[11];
    const float *Wih2 = w[12], *Whh2 = w[13], *bih2 = w[14], *bhh2 = w[15];
    const float *dWa = w[16], *dba = w[17], *dWb = w[18], *dbb = w[19];

    float *p_dis, *p_stats, *p_Xc, *p_gates, *p_y1, *p_h2f, *p_emb, *p_Ps, *p_Pt;
    cudaGetSymbolAddress((void**)&p_dis, g_dis);
    cudaGetSymbolAddress((void**)&p_stats, g_stats);
    cudaGetSymbolAddress((void**)&p_Xc, g_Xc);
    cudaGetSymbolAddress((void**)&p_gates, g_gates);
    cudaGetSymbolAddress((void**)&p_y1, g_y1);
    cudaGetSymbolAddress((void**)&p_h2f, g_h2f);
    cudaGetSymbolAddress((void**)&p_emb, g_emb);
    cudaGetSymbolAddress((void**)&p_Ps, g_Ps);
    cudaGetSymbolAddress((void**)&p_Pt, g_Pt);

    const int lstm_smem = (256 * 68 + 2 * 64 * 68) * 4;  // 104448 B
    cudaFuncSetAttribute(k_lstm_mma, cudaFuncAttributeMaxDynamicSharedMemorySize, lstm_smem);

    // --- graph normalization ---
    k_zero<<<(N_BIGC + 255) / 256, 256>>>(p_dis, N_BIGC);
    k_deg<<<(E_MAIN + 255) / 256, 256>>>(ei, ea);
    k_dis<<<(N_BIGC + 255) / 256, 256>>>();
    k_norm<<<(E_MAIN + 255) / 256, 256>>>(ei, ea);

    const int NB64 = N_BIGC * HIDC;
    dim3 g64((N_BIGC + 127) / 128), b16(16, 16);

    // --- GCN layer 1 ---
    k_zero<<<1, 128>>>(p_stats, 128);
    k_sgemm64_gcn<<<g64, b16>>>(x, W1, N_BIGC, IN_CC, IN_CC);
    k_scatter<<<(E_MAIN * 16 + 255) / 256, 256>>>(ei);
    k_brs<<<N_BIGC / 256, 256>>>(b1);
    k_bnfinal<<<1, 64>>>(g1, be1);
    k_bnapply<<<(NB64 + 255) / 256, 256>>>(0);

    // --- GCN layer 2 ---
    k_zero<<<1, 128>>>(p_stats, 128);
    k_sgemm64_gcn<<<g64, b16>>>(p_Xc, W2, N_BIGC, HIDC, 2 * HIDC);
    k_scatter<<<(E_MAIN * 16 + 255) / 256, 256>>>(ei);
    k_brs<<<N_BIGC / 256, 256>>>(b2);
    k_bnfinal<<<1, 64>>>(g2, be2);
    k_bnapply<<<(NB64 + 255) / 256, 256>>>(64);

    // --- LSTM 1: tf32 input-transform GEMM + tensor-core recurrence ---
    {
        dim3 grid(2, (N_BIGC + 127) / 128);
        k_tf32gemm<1><<<grid, 256>>>(p_Xc, Wih1, bih1, bhh1, p_gates,
                                     N_BIGC, 4 * HIDC, 2 * HIDC,
                                     2 * HIDC, 2 * HIDC, 4 * HIDC);
        dim3 gl((N_NODESC + 63) / 64);
        k_lstm_mma<<<gl, 256, lstm_smem>>>(p_gates, Whh1, p_y1, 0, N_NODESC);
    }

    // --- LSTM 2 ---
    {
        dim3 grid(2, (N_BIGC + 127) / 128);
        k_tf32gemm<1><<<grid, 256>>>(p_y1, Wih2, bih2, bhh2, p_gates,
                                     N_BIGC, 4 * HIDC, HIDC,
                                     HIDC, HIDC, 4 * HIDC);
        dim3 gl((N_NODESC + 63) / 64);
        k_lstm_mma<<<gl, 256, lstm_smem>>>(p_gates, Whh2, 0, p_h2f, N_NODESC);
    }

    // --- node embedding + decoder projections (tf32) ---
    k_emb<<<(N_NODESC * DHC + 255) / 256, 256>>>(x);
    {
        dim3 grid((DHC + 127) / 128, (N_NODESC + 127) / 128);
        k_tf32gemm<0><<<grid, 256>>>(p_emb, dWa, dba, 0, p_Ps,
                                     N_NODESC, DHC, DHC, DHC, DHC, PSTRIDE);
        k_tf32gemm<0><<<grid, 256>>>(p_emb, dWa + DHC * DHC, 0, 0, p_Pt,
                                     N_NODESC, DHC, DHC, DHC, DHC, PSTRIDE);
    }

    // --- edge decoder ---
    k_edge<<<(E_DECC * 32 + 255) / 256, 256>>>(ewi, dWb, dbb, (float*)d_out);
}

// round 5
// speedup vs baseline: 1.3393x; 1.3393x over previous
#include <cuda_runtime.h>
#include <math.h>

#define N_NODESC 20000
#define WINDOWC  8
#define N_BIGC   160000
#define IN_CC    8
#define HIDC     64
#define E_MAIN   1600000
#define E_DECC   500000
#define DHC      143
#define PSTRIDE  144

// ---------------- scratch (static device globals; no allocation) ----------------
__device__ float g_dis[N_BIGC];
__device__ float g_h[N_BIGC * HIDC];
__device__ float g_agg[N_BIGC * HIDC];        // relu output of gather
__device__ float g_Xc[N_BIGC * 2 * HIDC];
__device__ float g_gates[N_BIGC * 4 * HIDC];
__device__ float g_y1[N_BIGC * HIDC];
__device__ float g_h2f[N_NODESC * HIDC];
__device__ float g_emb[N_NODESC * DHC];
__device__ float g_Ps[N_NODESC * PSTRIDE];    // col 143 never written -> stays 0
__device__ float g_Pt[N_NODESC * PSTRIDE];
__device__ float g_stats[128];
__device__ float g_bnp[128];
// CSR (built once per launch, used by both GCN layers)
__device__ int2  g_csr[E_MAIN];               // (src_row, bitcast norm weight)
__device__ int   g_cnt[N_BIGC];
__device__ int   g_off[N_BIGC];
__device__ int   g_cur[N_BIGC];
__device__ int   g_total[1];

// ---------------- small utility kernels ----------------
__global__ void k_zero(float* p, int n) {
    int i = blockIdx.x * blockDim.x + threadIdx.x;
    if (i < n) p[i] = 0.f;
}

__global__ void k_deg(const int* __restrict__ ei, const float* __restrict__ ea) {
    int i = blockIdx.x * blockDim.x + threadIdx.x;
    if (i < E_MAIN) atomicAdd(&g_dis[ei[E_MAIN + i]], ea[i]);
}

__global__ void k_dis() {
    int i = blockIdx.x * blockDim.x + threadIdx.x;
    if (i < N_BIGC) g_dis[i] = rsqrtf(g_dis[i] + 1.0f);
}

// ---------------- CSR build ----------------
__global__ void k_count(const int* __restrict__ ei) {
    int i = blockIdx.x * blockDim.x + threadIdx.x;
    if (i < E_MAIN) atomicAdd(&g_cnt[ei[E_MAIN + i]], 1);
}

// warp-aggregated slot allocation (order-free "scan": ranges disjoint, cover [0,E))
__global__ void k_alloc() {
    int i = blockIdx.x * blockDim.x + threadIdx.x;
    if (i >= N_BIGC) return;                       // N_BIGC % 32 == 0: full warps
    int lane = threadIdx.x & 31;
    int c = g_cnt[i];
    int scan = c;
#pragma unroll
    for (int o = 1; o < 32; o <<= 1) {
        int v = __shfl_up_sync(0xffffffffu, scan, o);
        if (lane >= o) scan += v;
    }
    int excl = scan - c;
    int base = 0;
    if (lane == 31) base = atomicAdd(&g_total[0], scan);
    base = __shfl_sync(0xffffffffu, base, 31);
    g_off[i] = base + excl;
    g_cur[i] = base + excl;
}

__global__ void k_fill(const int* __restrict__ ei, const float* __restrict__ ea) {
    int e = blockIdx.x * blockDim.x + threadIdx.x;
    if (e >= E_MAIN) return;
    int r = ei[e], c = ei[E_MAIN + e];
    float w = g_dis[r] * ea[e] * g_dis[c];
    int pos = atomicAdd(&g_cur[c], 1);
    g_csr[pos] = make_int2(r, __float_as_int(w));
}

// ---------------- gather aggregation + bias + relu + BN-stats (no atomics on h) ----------------
// block 256 = 8 warps; each warp processes 8 consecutive nodes; grid = N_BIG/64 = 2500
__global__ void __launch_bounds__(256)
k_gather(const float* __restrict__ bias) {
    int warp = threadIdx.x >> 5, lane = threadIdx.x & 31;
    int n0 = (blockIdx.x * 8 + warp) * 8;
    float bc0 = bias[lane], bc1 = bias[lane + 32];
    float s0 = 0.f, q0 = 0.f, s1 = 0.f, q1 = 0.f;
#pragma unroll 1
    for (int k = 0; k < 8; k++) {
        int n = n0 + k;
        float d = g_dis[n];
        float d2 = d * d;
        float a0 = d2 * g_h[(size_t)n * 64 + lane];
        float a1 = d2 * g_h[(size_t)n * 64 + lane + 32];
        int beg = g_off[n], end = beg + g_cnt[n];
        for (int j = beg; j < end; j++) {
            int2 e = g_csr[j];
            float w = __int_as_float(e.y);
            a0 += w * g_h[(size_t)e.x * 64 + lane];
            a1 += w * g_h[(size_t)e.x * 64 + lane + 32];
        }
        float v0 = fmaxf(a0 + bc0, 0.f);
        float v1 = fmaxf(a1 + bc1, 0.f);
        g_agg[(size_t)n * 64 + lane]      = v0;
        g_agg[(size_t)n * 64 + lane + 32] = v1;
        s0 += v0; q0 += v0 * v0;
        s1 += v1; q1 += v1 * v1;
    }
    __shared__ float ss[64], sq[64];
    if (threadIdx.x < 64) { ss[threadIdx.x] = 0.f; sq[threadIdx.x] = 0.f; }
    __syncthreads();
    atomicAdd(&ss[lane], s0);      atomicAdd(&sq[lane], q0);
    atomicAdd(&ss[lane + 32], s1); atomicAdd(&sq[lane + 32], q1);
    __syncthreads();
    if (threadIdx.x < 64) {
        atomicAdd(&g_stats[threadIdx.x], ss[threadIdx.x]);
        atomicAdd(&g_stats[64 + threadIdx.x], sq[threadIdx.x]);
    }
}

__global__ void k_bnfinal(const float* __restrict__ gam, const float* __restrict__ bet) {
    int c = threadIdx.x;
    if (c < 64) {
        float inv_n = 1.f / (float)N_BIGC;
        float m = g_stats[c] * inv_n;
        float var = g_stats[64 + c] * inv_n - m * m;
        float a = rsqrtf(var + 1e-5f) * gam[c];
        g_bnp[c] = a;
        g_bnp[64 + c] = bet[c] - m * a;
    }
}

// apply BN (reads g_agg) into Xc[:, off:off+64]
__global__ void k_bnapply(int off) {
    int i = blockIdx.x * blockDim.x + threadIdx.x;
    if (i < N_BIGC * HIDC) {
        int c = i & 63, r = i >> 6;
        g_Xc[(size_t)r * 128 + off + c] = g_agg[i] * g_bnp[c] + g_bnp[64 + c];
    }
}

// ---------------- tf32 helpers ----------------
__device__ __forceinline__ unsigned f2tf(float f) {
    unsigned u;
    asm("cvt.rna.tf32.f32 %0, %1;" : "=r"(u) : "f"(f));
    return u;
}

#define MMA_TF32(c0,c1,c2,c3,a0,a1,a2,a3,b0,b1)                              \
    asm volatile("mma.sync.aligned.m16n8k8.row.col.f32.tf32.tf32.f32 "       \
                 "{%0,%1,%2,%3}, {%4,%5,%6,%7}, {%8,%9}, {%0,%1,%2,%3};"     \
                 : "+f"(c0), "+f"(c1), "+f"(c2), "+f"(c3)                    \
                 : "r"(a0), "r"(a1), "r"(a2), "r"(a3), "r"(b0), "r"(b1))

// ---------------- tf32 tensor-core GEMM ----------------
// C[M,N] = A[M,K] @ op(B) + bias1 + bias2
// BT=1: B is [N,K] row-major (A@B^T).  BT=0: B is [K,N] row-major.
template <int BT>
__global__ void __launch_bounds__(256, 2)
k_tf32gemm(const float* __restrict__ A, const float* __restrict__ B,
           const float* __restrict__ bias1, const float* __restrict__ bias2,
           float* __restrict__ C, int M, int N, int K,
           int lda, int ldb, int ldc) {
    __shared__ unsigned As[128][33];
    __shared__ unsigned Bs[128][33];
    int tid = threadIdx.x;
    int warp = tid >> 5, lane = tid & 31;
    int wm = warp >> 2, wn = warp & 3;
    int rowBase = blockIdx.y * 128, colBase = blockIdx.x * 128;
    int lr = lane >> 2, lc = lane & 3;

    float c[4][4][4];
#pragma unroll
    for (int mi = 0; mi < 4; mi++)
#pragma unroll
        for (int ni = 0; ni < 4; ni++)
#pragma unroll
            for (int q = 0; q < 4; q++) c[mi][ni][q] = 0.f;

    for (int k0 = 0; k0 < K; k0 += 32) {
#pragma unroll
        for (int q = 0; q < 16; q++) {
            int idx = q * 256 + tid;
            int r = idx >> 5, kk = idx & 31;
            int gr = rowBase + r, gk = k0 + kk;
            float v = (gr < M && gk < K) ? A[(size_t)gr * lda + gk] : 0.f;
            As[r][kk] = f2tf(v);
        }
        if (BT) {
#pragma unroll
            for (int q = 0; q < 16; q++) {
                int idx = q * 256 + tid;
                int n = idx >> 5, kk = idx & 31;
                int gn = colBase + n, gk = k0 + kk;
                float v = (gn < N && gk < K) ? B[(size_t)gn * ldb + gk] : 0.f;
                Bs[n][kk] = f2tf(v);
            }
        } else {
#pragma unroll
            for (int q = 0; q < 16; q++) {
                int idx = q * 256 + tid;
                int n = idx & 127, kk = idx >> 7;
                int gn = colBase + n, gk = k0 + kk;
                float v = (gn < N && gk < K) ? B[(size_t)gk * ldb + gn] : 0.f;
                Bs[n][kk] = f2tf(v);
            }
        }
        __syncthreads();

#pragma unroll
        for (int ks = 0; ks < 4; ks++) {
            int k8 = ks * 8;
            unsigned a[4][4], b[4][2];
#pragma unroll
            for (int mi = 0; mi < 4; mi++) {
                int r0 = wm * 64 + mi * 16 + lr;
                a[mi][0] = As[r0][k8 + lc];
                a[mi][1] = As[r0 + 8][k8 + lc];
                a[mi][2] = As[r0][k8 + lc + 4];
                a[mi][3] = As[r0 + 8][k8 + lc + 4];
            }
#pragma unroll
            for (int ni = 0; ni < 4; ni++) {
                int n0 = wn * 32 + ni * 8 + lr;
                b[ni][0] = Bs[n0][k8 + lc];
                b[ni][1] = Bs[n0][k8 + lc + 4];
            }
#pragma unroll
            for (int mi = 0; mi < 4; mi++)
#pragma unroll
                for (int ni = 0; ni < 4; ni++)
                    MMA_TF32(c[mi][ni][0], c[mi][ni][1], c[mi][ni][2], c[mi][ni][3],
                             a[mi][0], a[mi][1], a[mi][2], a[mi][3],
                             b[ni][0], b[ni][1]);
        }
        __syncthreads();
    }

#pragma unroll
    for (int mi = 0; mi < 4; mi++) {
#pragma unroll
        for (int ni = 0; ni < 4; ni++) {
            int gr0 = rowBase + wm * 64 + mi * 16 + lr;
            int gc0 = colBase + wn * 32 + ni * 8 + lc * 2;
#pragma unroll
            for (int q = 0; q < 4; q++) {
                int gr = gr0 + (q >> 1) * 8;
                int gc = gc0 + (q & 1);
                if (gr < M && gc < N) {
                    float b = 0.f;
                    if (bias1) b += bias1[gc];
                    if (bias2) b += bias2[gc];
                    C[(size_t)gr * ldc + gc] = c[mi][ni][q] + b;
                }
            }
        }
    }
}

// ---------------- SGEMM N=64: h = A@B ----------------
__global__ void k_sgemm64_gcn(const float* __restrict__ A, const float* __restrict__ B,
                              int M, int K, int lda) {
    __shared__ float As[8][132];
    __shared__ float Bs[8][68];
    int tx = threadIdx.x, ty = threadIdx.y;
    int tid = ty * 16 + tx;
    int rowBase = blockIdx.x * 128;
    float acc[8][4];
#pragma unroll
    for (int i = 0; i < 8; i++)
#pragma unroll
        for (int j = 0; j < 4; j++) acc[i][j] = 0.f;

    for (int k0 = 0; k0 < K; k0 += 8) {
#pragma unroll
        for (int q = 0; q < 4; q++) {
            int idx = q * 256 + tid;
            int r = idx >> 3, kk = idx & 7;
            int gr = rowBase + r, gk = k0 + kk;
            As[kk][r] = (gr < M && gk < K) ? A[(size_t)gr * lda + gk] : 0.f;
        }
#pragma unroll
        for (int q = 0; q < 2; q++) {
            int idx = q * 256 + tid;
            int cc = idx & 63, kk = idx >> 6;
            int gk = k0 + kk;
            Bs[kk][cc] = (gk < K) ? B[(size_t)gk * 64 + cc] : 0.f;
        }
        __syncthreads();
#pragma unroll
        for (int kk = 0; kk < 8; kk++) {
            float a[8], b[4];
            *(float4*)(a)     = *(const float4*)&As[kk][ty * 4];
            *(float4*)(a + 4) = *(const float4*)&As[kk][64 + ty * 4];
            *(float4*)(b)     = *(const float4*)&Bs[kk][tx * 4];
#pragma unroll
            for (int i = 0; i < 8; i++)
#pragma unroll
                for (int j = 0; j < 4; j++) acc[i][j] += a[i] * b[j];
        }
        __syncthreads();
    }

#pragma unroll
    for (int i = 0; i < 8; i++) {
        int gr = rowBase + ((i < 4) ? (ty * 4 + i) : (64 + ty * 4 + i - 4));
        if (gr < M) {
#pragma unroll
            for (int j = 0; j < 4; j++) {
                int gc = tx * 4 + j;
                g_h[(size_t)gr * 64 + gc] = acc[i][j];
            }
        }
    }
}

// ---------------- fused LSTM recurrence (all 8 timesteps, scalar R3 version) ----------------
__global__ void k_lstm(const float* __restrict__ gates, const float* __restrict__ Whh,
                       float* __restrict__ y, float* __restrict__ hfinal, int nrows) {
    extern __shared__ float sm[];
    float* sW = sm;                 // [256][68] gate-major, padded
    float* hb = sm + 256 * 68;      // [2][64][68]
    int tx = threadIdx.x, ty = threadIdx.y;
    int tid = ty * 64 + tx;
    for (int idx = tid; idx < 256 * 64; idx += 256) {
        int g = idx >> 6, k = idx & 63;
        sW[g * 68 + k] = Whh[idx];
    }
    for (int idx = tid; idx < 2 * 64 * 68; idx += 256) hb[idx] = 0.f;
    __syncthreads();

    int row0 = blockIdx.x * 64;
    float cst[16];
#pragma unroll
    for (int i = 0; i < 16; i++) cst[i] = 0.f;
    int cur = 0;

    for (int t = 0; t < 8; t++) {
        const float* gt = gates + (size_t)t * nrows * 256;
        const float* hbc = hb + cur * 64 * 68;
        float* hbn = hb + (cur ^ 1) * 64 * 68;
#pragma unroll
        for (int ch = 0; ch < 4; ch++) {
            int lr0 = ty * 16 + ch * 4;
            float ai[4], af[4], ag[4], ao[4];
#pragma unroll
            for (int r = 0; r < 4; r++) {
                int grow = row0 + lr0 + r;
                if (grow < nrows) {
                    const float* gp = gt + (size_t)grow * 256;
                    ai[r] = gp[tx]; af[r] = gp[64 + tx];
                    ag[r] = gp[128 + tx]; ao[r] = gp[192 + tx];
                } else { ai[r] = af[r] = ag[r] = ao[r] = 0.f; }
            }
#pragma unroll
            for (int k0 = 0; k0 < 64; k0 += 4) {
                float4 wi = *(const float4*)&sW[(size_t)tx * 68 + k0];
                float4 wf = *(const float4*)&sW[(size_t)(64 + tx) * 68 + k0];
                float4 wg = *(const float4*)&sW[(size_t)(128 + tx) * 68 + k0];
                float4 wo = *(const float4*)&sW[(size_t)(192 + tx) * 68 + k0];
#pragma unroll
                for (int r = 0; r < 4; r++) {
                    float4 h4 = *(const float4*)&hbc[(size_t)(lr0 + r) * 68 + k0];
                    ai[r] += h4.x * wi.x + h4.y * wi.y + h4.z * wi.z + h4.w * wi.w;
                    af[r] += h4.x * wf.x + h4.y * wf.y + h4.z * wf.z + h4.w * wf.w;
                    ag[r] += h4.x * wg.x + h4.y * wg.y + h4.z * wg.z + h4.w * wg.w;
                    ao[r] += h4.x * wo.x + h4.y * wo.y + h4.z * wo.z + h4.w * wo.w;
                }
            }
#pragma unroll
            for (int r = 0; r < 4; r++) {
                int grow = row0 + lr0 + r;
                float ig = 1.f / (1.f + expf(-ai[r]));
                float fg = 1.f / (1.f + expf(-af[r]));
                float gg = tanhf(ag[r]);
                float og = 1.f / (1.f + expf(-ao[r]));
                float c = fg * cst[ch * 4 + r] + ig * gg;
                cst[ch * 4 + r] = c;
                float h = og * tanhf(c);
                hbn[(size_t)(lr0 + r) * 68 + tx] = h;
                if (grow < nrows) {
                    if (y) y[((size_t)t * nrows + grow) * 64 + tx] = h;
                    if (t == 7 && hfinal) hfinal[(size_t)grow * 64 + tx] = h;
                }
            }
        }
        cur ^= 1;
        __syncthreads();
    }
}

// ---------------- node embedding assembly ----------------
__global__ void k_emb(const float* __restrict__ x) {
    int i = blockIdx.x * blockDim.x + threadIdx.x;
    if (i >= N_NODESC * DHC) return;
    int b = i / DHC, j = i - b * DHC;
    float v;
    if (j < 64)       v = g_y1[((size_t)7 * N_NODESC + b) * 64 + j];
    else if (j < 128) v = g_h2f[(size_t)b * 64 + (j - 64)];
    else if (j < 136) v = x[(size_t)b * 8 + (j - 128)];
    else { int t = j - 135; v = x[((size_t)t * N_NODESC + b) * 8 + 7]; }
    g_emb[i] = v;
}

// ---------------- edge decoder: warp per edge, float4 ----------------
__global__ void k_edge(const int* __restrict__ ewi, const float* __restrict__ dWb,
                       const float* __restrict__ dbb, float* __restrict__ out) {
    __shared__ float sw[PSTRIDE];
    if (threadIdx.x < PSTRIDE) sw[threadIdx.x] = (threadIdx.x < DHC) ? dWb[threadIdx.x] : 0.f;
    __syncthreads();
    int warp = (blockIdx.x * blockDim.x + threadIdx.x) >> 5;
    int lane = threadIdx.x & 31;
    if (warp >= E_DECC) return;
    int s = ewi[warp], tg = ewi[E_DECC + warp];
    const float4* ps = (const float4*)(g_Ps + (size_t)s * PSTRIDE);
    const float4* pt = (const float4*)(g_Pt + (size_t)tg * PSTRIDE);
    const float4* sw4 = (const float4*)sw;
    float acc = 0.f;
    {
        float4 a = ps[lane], b = pt[lane], w = sw4[lane];
        acc += fmaxf(a.x + b.x, 0.f) * w.x + fmaxf(a.y + b.y, 0.f) * w.y
             + fmaxf(a.z + b.z, 0.f) * w.z + fmaxf(a.w + b.w, 0.f) * w.w;
        if (lane < 4) {
            float4 a2 = ps[lane + 32], b2 = pt[lane + 32], w2 = sw4[lane + 32];
            acc += fmaxf(a2.x + b2.x, 0.f) * w2.x + fmaxf(a2.y + b2.y, 0.f) * w2.y
                 + fmaxf(a2.z + b2.z, 0.f) * w2.z + fmaxf(a2.w + b2.w, 0.f) * w2.w;
        }
    }
#pragma unroll
    for (int o = 16; o; o >>= 1) acc += __shfl_down_sync(0xffffffffu, acc, o);
    if (lane == 0) out[warp] = acc + dbb[0];
}

// ---------------- host ----------------
extern "C" void kernel_launch(void* const* d_in, const int* in_sizes, int n_in,
                              void* d_out, int out_size) {
    const float *x = 0, *ea = 0;
    const int *ei = 0, *ewi = 0;
    const float* w[20] = {0};
    int wi = 0;
    for (int i = 0; i < n_in; i++) {
        int s = in_sizes[i];
        if      (s == N_BIGC * IN_CC) x   = (const float*)d_in[i];
        else if (s == E_MAIN)         ea  = (const float*)d_in[i];
        else if (s == 2 * E_MAIN)     ei  = (const int*)d_in[i];
        else if (s == 2 * E_DECC)     ewi = (const int*)d_in[i];
        else if (wi < 20)             w[wi++] = (const float*)d_in[i];
    }
    const float *W1 = w[0], *b1 = w[1], *g1 = w[2], *be1 = w[3];
    const float *W2 = w[4], *b2 = w[5], *g2 = w[6], *be2 = w[7];
    const float *Wih1 = w[8], *Whh1 = w[9], *bih1 = w[10], *bhh1 = w[11];
    const float *Wih2 = w[12], *Whh2 = w[13], *bih2 = w[14], *bhh2 = w[15];
    const float *dWa = w[16], *dba = w[17], *dWb = w[18], *dbb = w[19];

    float *p_dis, *p_stats, *p_Xc, *p_gates, *p_y1, *p_h2f, *p_emb, *p_Ps, *p_Pt;
    int *p_cnt, *p_total;
    cudaGetSymbolAddress((void**)&p_dis, g_dis);
    cudaGetSymbolAddress((void**)&p_stats, g_stats);
    cudaGetSymbolAddress((void**)&p_Xc, g_Xc);
    cudaGetSymbolAddress((void**)&p_gates, g_gates);
    cudaGetSymbolAddress((void**)&p_y1, g_y1);
    cudaGetSymbolAddress((void**)&p_h2f, g_h2f);
    cudaGetSymbolAddress((void**)&p_emb, g_emb);
    cudaGetSymbolAddress((void**)&p_Ps, g_Ps);
    cudaGetSymbolAddress((void**)&p_Pt, g_Pt);
    cudaGetSymbolAddress((void**)&p_cnt, g_cnt);
    cudaGetSymbolAddress((void**)&p_total, g_total);

    const int lstm_smem = (256 * 68 + 2 * 64 * 68) * 4;  // 104448 B
    cudaFuncSetAttribute(k_lstm, cudaFuncAttributeMaxDynamicSharedMemorySize, lstm_smem);

    // --- graph normalization + CSR build (shared by both GCN layers) ---
    k_zero<<<(N_BIGC + 255) / 256, 256>>>(p_dis, N_BIGC);
    k_zero<<<(N_BIGC + 255) / 256, 256>>>((float*)p_cnt, N_BIGC);   // int 0 == float 0 bits
    k_zero<<<1, 32>>>((float*)p_total, 1);
    k_deg<<<(E_MAIN + 255) / 256, 256>>>(ei, ea);
    k_dis<<<(N_BIGC + 255) / 256, 256>>>();
    k_count<<<(E_MAIN + 255) / 256, 256>>>(ei);
    k_alloc<<<(N_BIGC + 255) / 256, 256>>>();
    k_fill<<<(E_MAIN + 255) / 256, 256>>>(ei, ea);

    const int NB64 = N_BIGC * HIDC;
    dim3 g64((N_BIGC + 127) / 128), b16(16, 16);

    // --- GCN layer 1 ---
    k_zero<<<1, 128>>>(p_stats, 128);
    k_sgemm64_gcn<<<g64, b16>>>(x, W1, N_BIGC, IN_CC, IN_CC);
    k_gather<<<N_BIGC / 64, 256>>>(b1);
    k_bnfinal<<<1, 64>>>(g1, be1);
    k_bnapply<<<(NB64 + 255) / 256, 256>>>(0);

    // --- GCN layer 2 ---
    k_zero<<<1, 128>>>(p_stats, 128);
    k_sgemm64_gcn<<<g64, b16>>>(p_Xc, W2, N_BIGC, HIDC, 2 * HIDC);
    k_gather<<<N_BIGC / 64, 256>>>(b2);
    k_bnfinal<<<1, 64>>>(g2, be2);
    k_bnapply<<<(NB64 + 255) / 256, 256>>>(64);

    // --- LSTM 1: tf32 input-transform GEMM + fused scalar recurrence ---
    {
        dim3 grid(2, (N_BIGC + 127) / 128);
        k_tf32gemm<1><<<grid, 256>>>(p_Xc, Wih1, bih1, bhh1, p_gates,
                                     N_BIGC, 4 * HIDC, 2 * HIDC,
                                     2 * HIDC, 2 * HIDC, 4 * HIDC);
        dim3 gl((N_NODESC + 63) / 64), bl(64, 4);
        k_lstm<<<gl, bl, lstm_smem>>>(p_gates, Whh1, p_y1, 0, N_NODESC);
    }

    // --- LSTM 2 ---
    {
        dim3 grid(2, (N_BIGC + 127) / 128);
        k_tf32gemm<1><<<grid, 256>>>(p_y1, Wih2, bih2, bhh2, p_gates,
                                     N_BIGC, 4 * HIDC, HIDC,
                                     HIDC, HIDC, 4 * HIDC);
        dim3 gl((N_NODESC + 63) / 64), bl(64, 4);
        k_lstm<<<gl, bl, lstm_smem>>>(p_gates, Whh2, 0, p_h2f, N_NODESC);
    }

    // --- node embedding + decoder projections (tf32) ---
    k_emb<<<(N_NODESC * DHC + 255) / 256, 256>>>(x);
    {
        dim3 grid((DHC + 127) / 128, (N_NODESC + 127) / 128);
        k_tf32gemm<0><<<grid, 256>>>(p_emb, dWa, dba, 0, p_Ps,
                                     N_NODESC, DHC, DHC, DHC, DHC, PSTRIDE);
        k_tf32gemm<0><<<grid, 256>>>(p_emb, dWa + DHC * DHC, 0, 0, p_Pt,
                                     N_NODESC, DHC, DHC, DHC, DHC, PSTRIDE);
    }

    // --- edge decoder ---
    k_edge<<<(E_DECC * 32 + 255) / 256, 256>>>(ewi, dWb, dbb, (float*)d_out);
}

// round 6
// speedup vs baseline: 1.6098x; 1.2020x over previous
#include <cuda_runtime.h>
#include <math.h>

#define N_NODESC 20000
#define WINDOWC  8
#define N_BIGC   160000
#define IN_CC    8
#define HIDC     64
#define E_MAIN   1600000
#define E_DECC   500000
#define DHC      143
#define PSTRIDE  144

typedef unsigned long long u64;

// ---------------- scratch (static device globals; no allocation) ----------------
__device__ float g_dis[N_BIGC];
__device__ float g_h[N_BIGC * HIDC];
__device__ float g_agg[N_BIGC * HIDC];
__device__ float g_Xc[N_BIGC * 2 * HIDC];
__device__ float g_gates[N_BIGC * 4 * HIDC];
__device__ float g_y1[N_BIGC * HIDC];
__device__ float g_h2f[N_NODESC * HIDC];
__device__ float g_emb[N_NODESC * DHC];
__device__ float g_Ps[N_NODESC * PSTRIDE];    // col 143 never written -> stays 0
__device__ float g_Pt[N_NODESC * PSTRIDE];
__device__ float g_stats[128];
__device__ float g_bnp[128];
// CSR (built once per launch, used by both GCN layers)
__device__ int2  g_csr[E_MAIN];               // (src_row, bitcast norm weight)
__device__ int   g_cnt[N_BIGC];
__device__ int   g_off[N_BIGC];
__device__ int   g_cur[N_BIGC];
__device__ int   g_total[1];

// ---------------- packed f32x2 helpers ----------------
__device__ __forceinline__ u64 fma2(u64 a, u64 b, u64 c) {
    u64 d;
    asm("fma.rn.f32x2 %0, %1, %2, %3;" : "=l"(d) : "l"(a), "l"(b), "l"(c));
    return d;
}
__device__ __forceinline__ u64 pack2(float lo, float hi) {
    u64 p;
    asm("mov.b64 %0, {%1, %2};" : "=l"(p) : "f"(lo), "f"(hi));
    return p;
}
__device__ __forceinline__ float sum2(u64 p) {
    float lo, hi;
    asm("mov.b64 {%0, %1}, %2;" : "=f"(lo), "=f"(hi) : "l"(p));
    return lo + hi;
}

// ---------------- init: zero dis/cnt/total/stats in one pass ----------------
__global__ void k_init() {
    int i = blockIdx.x * blockDim.x + threadIdx.x;
    if (i < N_BIGC) { g_dis[i] = 0.f; g_cnt[i] = 0; }
    if (i < 128) g_stats[i] = 0.f;
    if (i == 0) g_total[0] = 0;
}

// one edge pass: weighted degree + CSR counts
__global__ void k_degcount(const int* __restrict__ ei, const float* __restrict__ ea) {
    int i = blockIdx.x * blockDim.x + threadIdx.x;
    if (i < E_MAIN) {
        int c = ei[E_MAIN + i];
        atomicAdd(&g_dis[c], ea[i]);
        atomicAdd(&g_cnt[c], 1);
    }
}

// dis = rsqrt(deg+1); warp-aggregated CSR slot allocation (order-free)
__global__ void k_disalloc() {
    int i = blockIdx.x * blockDim.x + threadIdx.x;
    if (i >= N_BIGC) return;                       // N_BIGC % 256 == 0: full warps
    g_dis[i] = rsqrtf(g_dis[i] + 1.0f);
    int lane = threadIdx.x & 31;
    int c = g_cnt[i];
    int scan = c;
#pragma unroll
    for (int o = 1; o < 32; o <<= 1) {
        int v = __shfl_up_sync(0xffffffffu, scan, o);
        if (lane >= o) scan += v;
    }
    int excl = scan - c;
    int base = 0;
    if (lane == 31) base = atomicAdd(&g_total[0], scan);
    base = __shfl_sync(0xffffffffu, base, 31);
    g_off[i] = base + excl;
    g_cur[i] = base + excl;
}

__global__ void k_fill(const int* __restrict__ ei, const float* __restrict__ ea) {
    int e = blockIdx.x * blockDim.x + threadIdx.x;
    if (e >= E_MAIN) return;
    int r = ei[e], c = ei[E_MAIN + e];
    float w = g_dis[r] * ea[e] * g_dis[c];
    int pos = atomicAdd(&g_cur[c], 1);
    g_csr[pos] = make_int2(r, __float_as_int(w));
}

// ---------------- gather aggregation + bias + relu + BN-stats ----------------
// block 256 = 8 warps; warp processes 8 consecutive nodes; edge loop unrolled x2 for MLP
__global__ void __launch_bounds__(256)
k_gather(const float* __restrict__ bias) {
    int warp = threadIdx.x >> 5, lane = threadIdx.x & 31;
    int n0 = (blockIdx.x * 8 + warp) * 8;
    float bc0 = bias[lane], bc1 = bias[lane + 32];
    float s0 = 0.f, q0 = 0.f, s1 = 0.f, q1 = 0.f;
#pragma unroll 1
    for (int k = 0; k < 8; k++) {
        int n = n0 + k;
        float d = g_dis[n];
        float d2 = d * d;
        float a0 = d2 * g_h[(size_t)n * 64 + lane];
        float a1 = d2 * g_h[(size_t)n * 64 + lane + 32];
        float b0 = 0.f, b1 = 0.f;
        int beg = g_off[n], end = beg + g_cnt[n];
        int j = beg;
        for (; j + 2 <= end; j += 2) {
            int2 e0 = g_csr[j], e1 = g_csr[j + 1];
            float w0 = __int_as_float(e0.y), w1 = __int_as_float(e1.y);
            float x00 = g_h[(size_t)e0.x * 64 + lane];
            float x01 = g_h[(size_t)e0.x * 64 + lane + 32];
            float x10 = g_h[(size_t)e1.x * 64 + lane];
            float x11 = g_h[(size_t)e1.x * 64 + lane + 32];
            a0 += w0 * x00; a1 += w0 * x01;
            b0 += w1 * x10; b1 += w1 * x11;
        }
        if (j < end) {
            int2 e = g_csr[j];
            float w = __int_as_float(e.y);
            a0 += w * g_h[(size_t)e.x * 64 + lane];
            a1 += w * g_h[(size_t)e.x * 64 + lane + 32];
        }
        float v0 = fmaxf(a0 + b0 + bc0, 0.f);
        float v1 = fmaxf(a1 + b1 + bc1, 0.f);
        g_agg[(size_t)n * 64 + lane]      = v0;
        g_agg[(size_t)n * 64 + lane + 32] = v1;
        s0 += v0; q0 += v0 * v0;
        s1 += v1; q1 += v1 * v1;
    }
    __shared__ float ss[64], sq[64];
    if (threadIdx.x < 64) { ss[threadIdx.x] = 0.f; sq[threadIdx.x] = 0.f; }
    __syncthreads();
    atomicAdd(&ss[lane], s0);      atomicAdd(&sq[lane], q0);
    atomicAdd(&ss[lane + 32], s1); atomicAdd(&sq[lane + 32], q1);
    __syncthreads();
    if (threadIdx.x < 64) {
        atomicAdd(&g_stats[threadIdx.x], ss[threadIdx.x]);
        atomicAdd(&g_stats[64 + threadIdx.x], sq[threadIdx.x]);
    }
}

// finalize BN params; self-zero stats for the next gather/replay
__global__ void k_bnfinal(const float* __restrict__ gam, const float* __restrict__ bet) {
    int c = threadIdx.x;
    if (c < 64) {
        float inv_n = 1.f / (float)N_BIGC;
        float m = g_stats[c] * inv_n;
        float var = g_stats[64 + c] * inv_n - m * m;
        float a = rsqrtf(var + 1e-5f) * gam[c];
        g_bnp[c] = a;
        g_bnp[64 + c] = bet[c] - m * a;
        g_stats[c] = 0.f;
        g_stats[64 + c] = 0.f;
    }
}

// apply BN (reads g_agg) into Xc[:, off:off+64], float4
__global__ void k_bnapply(int off) {
    int i = blockIdx.x * blockDim.x + threadIdx.x;
    if (i >= N_BIGC * 16) return;
    int r = i >> 4, c4 = i & 15;
    float4 v = ((const float4*)g_agg)[i];
    int c = c4 * 4;
    float4 o;
    o.x = v.x * g_bnp[c]     + g_bnp[64 + c];
    o.y = v.y * g_bnp[c + 1] + g_bnp[65 + c];
    o.z = v.z * g_bnp[c + 2] + g_bnp[66 + c];
    o.w = v.w * g_bnp[c + 3] + g_bnp[67 + c];
    ((float4*)(g_Xc + (size_t)r * 128 + off))[c4] = o;
}

// ---------------- tf32 helpers ----------------
__device__ __forceinline__ unsigned f2tf(float f) {
    unsigned u;
    asm("cvt.rna.tf32.f32 %0, %1;" : "=r"(u) : "f"(f));
    return u;
}

#define MMA_TF32(c0,c1,c2,c3,a0,a1,a2,a3,b0,b1)                              \
    asm volatile("mma.sync.aligned.m16n8k8.row.col.f32.tf32.tf32.f32 "       \
                 "{%0,%1,%2,%3}, {%4,%5,%6,%7}, {%8,%9}, {%0,%1,%2,%3};"     \
                 : "+f"(c0), "+f"(c1), "+f"(c2), "+f"(c3)                    \
                 : "r"(a0), "r"(a1), "r"(a2), "r"(a3), "r"(b0), "r"(b1))

// ---------------- tf32 tensor-core GEMM ----------------
template <int BT>
__global__ void __launch_bounds__(256, 2)
k_tf32gemm(const float* __restrict__ A, const float* __restrict__ B,
           const float* __restrict__ bias1, const float* __restrict__ bias2,
           float* __restrict__ C, int M, int N, int K,
           int lda, int ldb, int ldc) {
    __shared__ unsigned As[128][33];
    __shared__ unsigned Bs[128][33];
    int tid = threadIdx.x;
    int warp = tid >> 5, lane = tid & 31;
    int wm = warp >> 2, wn = warp & 3;
    int rowBase = blockIdx.y * 128, colBase = blockIdx.x * 128;
    int lr = lane >> 2, lc = lane & 3;

    float c[4][4][4];
#pragma unroll
    for (int mi = 0; mi < 4; mi++)
#pragma unroll
        for (int ni = 0; ni < 4; ni++)
#pragma unroll
            for (int q = 0; q < 4; q++) c[mi][ni][q] = 0.f;

    for (int k0 = 0; k0 < K; k0 += 32) {
#pragma unroll
        for (int q = 0; q < 16; q++) {
            int idx = q * 256 + tid;
            int r = idx >> 5, kk = idx & 31;
            int gr = rowBase + r, gk = k0 + kk;
            float v = (gr < M && gk < K) ? A[(size_t)gr * lda + gk] : 0.f;
            As[r][kk] = f2tf(v);
        }
        if (BT) {
#pragma unroll
            for (int q = 0; q < 16; q++) {
                int idx = q * 256 + tid;
                int n = idx >> 5, kk = idx & 31;
                int gn = colBase + n, gk = k0 + kk;
                float v = (gn < N && gk < K) ? B[(size_t)gn * ldb + gk] : 0.f;
                Bs[n][kk] = f2tf(v);
            }
        } else {
#pragma unroll
            for (int q = 0; q < 16; q++) {
                int idx = q * 256 + tid;
                int n = idx & 127, kk = idx >> 7;
                int gn = colBase + n, gk = k0 + kk;
                float v = (gn < N && gk < K) ? B[(size_t)gk * ldb + gn] : 0.f;
                Bs[n][kk] = f2tf(v);
            }
        }
        __syncthreads();

#pragma unroll
        for (int ks = 0; ks < 4; ks++) {
            int k8 = ks * 8;
            unsigned a[4][4], b[4][2];
#pragma unroll
            for (int mi = 0; mi < 4; mi++) {
                int r0 = wm * 64 + mi * 16 + lr;
                a[mi][0] = As[r0][k8 + lc];
                a[mi][1] = As[r0 + 8][k8 + lc];
                a[mi][2] = As[r0][k8 + lc + 4];
                a[mi][3] = As[r0 + 8][k8 + lc + 4];
            }
#pragma unroll
            for (int ni = 0; ni < 4; ni++) {
                int n0 = wn * 32 + ni * 8 + lr;
                b[ni][0] = Bs[n0][k8 + lc];
                b[ni][1] = Bs[n0][k8 + lc + 4];
            }
#pragma unroll
            for (int mi = 0; mi < 4; mi++)
#pragma unroll
                for (int ni = 0; ni < 4; ni++)
                    MMA_TF32(c[mi][ni][0], c[mi][ni][1], c[mi][ni][2], c[mi][ni][3],
                             a[mi][0], a[mi][1], a[mi][2], a[mi][3],
                             b[ni][0], b[ni][1]);
        }
        __syncthreads();
    }

#pragma unroll
    for (int mi = 0; mi < 4; mi++) {
#pragma unroll
        for (int ni = 0; ni < 4; ni++) {
            int gr0 = rowBase + wm * 64 + mi * 16 + lr;
            int gc0 = colBase + wn * 32 + ni * 8 + lc * 2;
#pragma unroll
            for (int q = 0; q < 4; q++) {
                int gr = gr0 + (q >> 1) * 8;
                int gc = gc0 + (q & 1);
                if (gr < M && gc < N) {
                    float b = 0.f;
                    if (bias1) b += bias1[gc];
                    if (bias2) b += bias2[gc];
                    C[(size_t)gr * ldc + gc] = c[mi][ni][q] + b;
                }
            }
        }
    }
}

// ---------------- SGEMM N=64: h = A@B ----------------
__global__ void k_sgemm64_gcn(const float* __restrict__ A, const float* __restrict__ B,
                              int M, int K, int lda) {
    __shared__ float As[8][132];
    __shared__ float Bs[8][68];
    int tx = threadIdx.x, ty = threadIdx.y;
    int tid = ty * 16 + tx;
    int rowBase = blockIdx.x * 128;
    float acc[8][4];
#pragma unroll
    for (int i = 0; i < 8; i++)
#pragma unroll
        for (int j = 0; j < 4; j++) acc[i][j] = 0.f;

    for (int k0 = 0; k0 < K; k0 += 8) {
#pragma unroll
        for (int q = 0; q < 4; q++) {
            int idx = q * 256 + tid;
            int r = idx >> 3, kk = idx & 7;
            int gr = rowBase + r, gk = k0 + kk;
            As[kk][r] = (gr < M && gk < K) ? A[(size_t)gr * lda + gk] : 0.f;
        }
#pragma unroll
        for (int q = 0; q < 2; q++) {
            int idx = q * 256 + tid;
            int cc = idx & 63, kk = idx >> 6;
            int gk = k0 + kk;
            Bs[kk][cc] = (gk < K) ? B[(size_t)gk * 64 + cc] : 0.f;
        }
        __syncthreads();
#pragma unroll
        for (int kk = 0; kk < 8; kk++) {
            float a[8], b[4];
            *(float4*)(a)     = *(const float4*)&As[kk][ty * 4];
            *(float4*)(a + 4) = *(const float4*)&As[kk][64 + ty * 4];
            *(float4*)(b)     = *(const float4*)&Bs[kk][tx * 4];
#pragma unroll
            for (int i = 0; i < 8; i++)
#pragma unroll
                for (int j = 0; j < 4; j++) acc[i][j] += a[i] * b[j];
        }
        __syncthreads();
    }

#pragma unroll
    for (int i = 0; i < 8; i++) {
        int gr = rowBase + ((i < 4) ? (ty * 4 + i) : (64 + ty * 4 + i - 4));
        if (gr < M) {
#pragma unroll
            for (int j = 0; j < 4; j++) {
                int gc = tx * 4 + j;
                g_h[(size_t)gr * 64 + gc] = acc[i][j];
            }
        }
    }
}

// ---------------- fused LSTM recurrence (all 8 timesteps, f32x2 packed FMA) ----------------
__global__ void k_lstm(const float* __restrict__ gates, const float* __restrict__ Whh,
                       float* __restrict__ y, float* __restrict__ hfinal, int nrows) {
    extern __shared__ float sm[];
    float* sW = sm;                 // [256][68] gate-major, padded (272B rows: 16B-aligned)
    float* hb = sm + 256 * 68;      // [2][64][68]
    int tx = threadIdx.x, ty = threadIdx.y;
    int tid = ty * 64 + tx;
    for (int idx = tid; idx < 256 * 64; idx += 256) {
        int g = idx >> 6, k = idx & 63;
        sW[g * 68 + k] = Whh[idx];
    }
    for (int idx = tid; idx < 2 * 64 * 68; idx += 256) hb[idx] = 0.f;
    __syncthreads();

    int row0 = blockIdx.x * 64;
    float cst[16];
#pragma unroll
    for (int i = 0; i < 16; i++) cst[i] = 0.f;
    int cur = 0;

    for (int t = 0; t < 8; t++) {
        const float* gt = gates + (size_t)t * nrows * 256;
        const float* hbc = hb + cur * 64 * 68;
        float* hbn = hb + (cur ^ 1) * 64 * 68;
#pragma unroll
        for (int ch = 0; ch < 4; ch++) {
            int lr0 = ty * 16 + ch * 4;
            u64 ai[4], af[4], ag[4], ao[4];
#pragma unroll
            for (int r = 0; r < 4; r++) {
                int grow = row0 + lr0 + r;
                if (grow < nrows) {
                    const float* gp = gt + (size_t)grow * 256;
                    ai[r] = pack2(gp[tx], 0.f);
                    af[r] = pack2(gp[64 + tx], 0.f);
                    ag[r] = pack2(gp[128 + tx], 0.f);
                    ao[r] = pack2(gp[192 + tx], 0.f);
                } else {
                    ai[r] = af[r] = ag[r] = ao[r] = 0ull;
                }
            }
#pragma unroll
            for (int k0 = 0; k0 < 64; k0 += 4) {
                ulonglong2 wi = *(const ulonglong2*)&sW[(size_t)tx * 68 + k0];
                ulonglong2 wf = *(const ulonglong2*)&sW[(size_t)(64 + tx) * 68 + k0];
                ulonglong2 wg = *(const ulonglong2*)&sW[(size_t)(128 + tx) * 68 + k0];
                ulonglong2 wo = *(const ulonglong2*)&sW[(size_t)(192 + tx) * 68 + k0];
#pragma unroll
                for (int r = 0; r < 4; r++) {
                    ulonglong2 h2 = *(const ulonglong2*)&hbc[(size_t)(lr0 + r) * 68 + k0];
                    ai[r] = fma2(h2.x, wi.x, ai[r]); ai[r] = fma2(h2.y, wi.y, ai[r]);
                    af[r] = fma2(h2.x, wf.x, af[r]); af[r] = fma2(h2.y, wf.y, af[r]);
                    ag[r] = fma2(h2.x, wg.x, ag[r]); ag[r] = fma2(h2.y, wg.y, ag[r]);
                    ao[r] = fma2(h2.x, wo.x, ao[r]); ao[r] = fma2(h2.y, wo.y, ao[r]);
                }
            }
#pragma unroll
            for (int r = 0; r < 4; r++) {
                int grow = row0 + lr0 + r;
                float iv = sum2(ai[r]), fv = sum2(af[r]);
                float gv = sum2(ag[r]), ov = sum2(ao[r]);
                float ig = 1.f / (1.f + expf(-iv));
                float fg = 1.f / (1.f + expf(-fv));
                float gg = tanhf(gv);
                float og = 1.f / (1.f + expf(-ov));
                float c = fg * cst[ch * 4 + r] + ig * gg;
                cst[ch * 4 + r] = c;
                float h = og * tanhf(c);
                hbn[(size_t)(lr0 + r) * 68 + tx] = h;
                if (grow < nrows) {
                    if (y) y[((size_t)t * nrows + grow) * 64 + tx] = h;
                    if (t == 7 && hfinal) hfinal[(size_t)grow * 64 + tx] = h;
                }
            }
        }
        cur ^= 1;
        __syncthreads();
    }
}

// ---------------- node embedding assembly ----------------
__global__ void k_emb(const float* __restrict__ x) {
    int i = blockIdx.x * blockDim.x + threadIdx.x;
    if (i >= N_NODESC * DHC) return;
    int b = i / DHC, j = i - b * DHC;
    float v;
    if (j < 64)       v = g_y1[((size_t)7 * N_NODESC + b) * 64 + j];
    else if (j < 128) v = g_h2f[(size_t)b * 64 + (j - 64)];
    else if (j < 136) v = x[(size_t)b * 8 + (j - 128)];
    else { int t = j - 135; v = x[((size_t)t * N_NODESC + b) * 8 + 7]; }
    g_emb[i] = v;
}

// ---------------- edge decoder: warp per edge, float4 ----------------
__global__ void k_edge(const int* __restrict__ ewi, const float* __restrict__ dWb,
                       const float* __restrict__ dbb, float* __restrict__ out) {
    __shared__ float sw[PSTRIDE];
    if (threadIdx.x < PSTRIDE) sw[threadIdx.x] = (threadIdx.x < DHC) ? dWb[threadIdx.x] : 0.f;
    __syncthreads();
    int warp = (blockIdx.x * blockDim.x + threadIdx.x) >> 5;
    int lane = threadIdx.x & 31;
    if (warp >= E_DECC) return;
    int s = ewi[warp], tg = ewi[E_DECC + warp];
    const float4* ps = (const float4*)(g_Ps + (size_t)s * PSTRIDE);
    const float4* pt = (const float4*)(g_Pt + (size_t)tg * PSTRIDE);
    const float4* sw4 = (const float4*)sw;
    float acc = 0.f;
    {
        float4 a = ps[lane], b = pt[lane], w = sw4[lane];
        acc += fmaxf(a.x + b.x, 0.f) * w.x + fmaxf(a.y + b.y, 0.f) * w.y
             + fmaxf(a.z + b.z, 0.f) * w.z + fmaxf(a.w + b.w, 0.f) * w.w;
        if (lane < 4) {
            float4 a2 = ps[lane + 32], b2 = pt[lane + 32], w2 = sw4[lane + 32];
            acc += fmaxf(a2.x + b2.x, 0.f) * w2.x + fmaxf(a2.y + b2.y, 0.f) * w2.y
                 + fmaxf(a2.z + b2.z, 0.f) * w2.z + fmaxf(a2.w + b2.w, 0.f) * w2.w;
        }
    }
#pragma unroll
    for (int o = 16; o; o >>= 1) acc += __shfl_down_sync(0xffffffffu, acc, o);
    if (lane == 0) out[warp] = acc + dbb[0];
}

// ---------------- host ----------------
extern "C" void kernel_launch(void* const* d_in, const int* in_sizes, int n_in,
                              void* d_out, int out_size) {
    const float *x = 0, *ea = 0;
    const int *ei = 0, *ewi = 0;
    const float* w[20] = {0};
    int wi = 0;
    for (int i = 0; i < n_in; i++) {
        int s = in_sizes[i];
        if      (s == N_BIGC * IN_CC) x   = (const float*)d_in[i];
        else if (s == E_MAIN)         ea  = (const float*)d_in[i];
        else if (s == 2 * E_MAIN)     ei  = (const int*)d_in[i];
        else if (s == 2 * E_DECC)     ewi = (const int*)d_in[i];
        else if (wi < 20)             w[wi++] = (const float*)d_in[i];
    }
    const float *W1 = w[0], *b1 = w[1], *g1 = w[2], *be1 = w[3];
    const float *W2 = w[4], *b2 = w[5], *g2 = w[6], *be2 = w[7];
    const float *Wih1 = w[8], *Whh1 = w[9], *bih1 = w[10], *bhh1 = w[11];
    const float *Wih2 = w[12], *Whh2 = w[13], *bih2 = w[14], *bhh2 = w[15];
    const float *dWa = w[16], *dba = w[17], *dWb = w[18], *dbb = w[19];

    float *p_Xc, *p_gates, *p_y1, *p_h2f, *p_emb, *p_Ps, *p_Pt;
    cudaGetSymbolAddress((void**)&p_Xc, g_Xc);
    cudaGetSymbolAddress((void**)&p_gates, g_gates);
    cudaGetSymbolAddress((void**)&p_y1, g_y1);
    cudaGetSymbolAddress((void**)&p_h2f, g_h2f);
    cudaGetSymbolAddress((void**)&p_emb, g_emb);
    cudaGetSymbolAddress((void**)&p_Ps, g_Ps);
    cudaGetSymbolAddress((void**)&p_Pt, g_Pt);

    const int lstm_smem = (256 * 68 + 2 * 64 * 68) * 4;  // 104448 B
    cudaFuncSetAttribute(k_lstm, cudaFuncAttributeMaxDynamicSharedMemorySize, lstm_smem);

    // --- graph normalization + CSR build (shared by both GCN layers) ---
    k_init<<<(N_BIGC + 255) / 256, 256>>>();
    k_degcount<<<(E_MAIN + 255) / 256, 256>>>(ei, ea);
    k_disalloc<<<(N_BIGC + 255) / 256, 256>>>();
    k_fill<<<(E_MAIN + 255) / 256, 256>>>(ei, ea);

    dim3 g64((N_BIGC + 127) / 128), b16(16, 16);

    // --- GCN layer 1 ---
    k_sgemm64_gcn<<<g64, b16>>>(x, W1, N_BIGC, IN_CC, IN_CC);
    k_gather<<<N_BIGC / 64, 256>>>(b1);
    k_bnfinal<<<1, 64>>>(g1, be1);
    k_bnapply<<<(N_BIGC * 16 + 255) / 256, 256>>>(0);

    // --- GCN layer 2 ---
    k_sgemm64_gcn<<<g64, b16>>>(p_Xc, W2, N_BIGC, HIDC, 2 * HIDC);
    k_gather<<<N_BIGC / 64, 256>>>(b2);
    k_bnfinal<<<1, 64>>>(g2, be2);
    k_bnapply<<<(N_BIGC * 16 + 255) / 256, 256>>>(64);

    // --- LSTM 1: tf32 input-transform GEMM + fused f32x2 recurrence ---
    {
        dim3 grid(2, (N_BIGC + 127) / 128);
        k_tf32gemm<1><<<grid, 256>>>(p_Xc, Wih1, bih1, bhh1, p_gates,
                                     N_BIGC, 4 * HIDC, 2 * HIDC,
                                     2 * HIDC, 2 * HIDC, 4 * HIDC);
        dim3 gl((N_NODESC + 63) / 64), bl(64, 4);
        k_lstm<<<gl, bl, lstm_smem>>>(p_gates, Whh1, p_y1, 0, N_NODESC);
    }

    // --- LSTM 2 ---
    {
        dim3 grid(2, (N_BIGC + 127) / 128);
        k_tf32gemm<1><<<grid, 256>>>(p_y1, Wih2, bih2, bhh2, p_gates,
                                     N_BIGC, 4 * HIDC, HIDC,
                                     HIDC, HIDC, 4 * HIDC);
        dim3 gl((N_NODESC + 63) / 64), bl(64, 4);
        k_lstm<<<gl, bl, lstm_smem>>>(p_gates, Whh2, 0, p_h2f, N_NODESC);
    }

    // --- node embedding + decoder projections (tf32) ---
    k_emb<<<(N_NODESC * DHC + 255) / 256, 256>>>(x);
    {
        dim3 grid((DHC + 127) / 128, (N_NODESC + 127) / 128);
        k_tf32gemm<0><<<grid, 256>>>(p_emb, dWa, dba, 0, p_Ps,
                                     N_NODESC, DHC, DHC, DHC, DHC, PSTRIDE);
        k_tf32gemm<0><<<grid, 256>>>(p_emb, dWa + DHC * DHC, 0, 0, p_Pt,
                                     N_NODESC, DHC, DHC, DHC, DHC, PSTRIDE);
    }

    // --- edge decoder ---
    k_edge<<<(E_DECC * 32 + 255) / 256, 256>>>(ewi, dWb, dbb, (float*)d_out);
}